// round 15
// baseline (speedup 1.0000x reference)
#include <cuda_runtime.h>
#include <cuda_bf16.h>
#include <math.h>
#include <cstdint>

#define N_NODES 100000
#define D 128
#define D_LAT 64
#define N_EDGES 1600000
#define SCAN_BLOCKS ((N_NODES + 255) / 256)   // 391
#define PERM_CAP 2400000                      // >= N_EDGES + 7*N_NODES

// Scratch (device globals: allocation-free, graph-capture safe).
// Feature buffers have one extra all-zero row at index N_NODES (sentinel for
// padded edges). Zero-initialized at module load; no kernel ever writes row N.
__device__ __nv_bfloat16  g_xbf[(size_t)(N_NODES + 1) * D];
__device__ __nv_bfloat16  g_aggr[(size_t)N_NODES * D];
__device__ __nv_bfloat16  g_hA[(size_t)(N_NODES + 1) * D];
__device__ __nv_bfloat16  g_hB[(size_t)(N_NODES + 1) * D];
__device__ float g_pool[D];
__device__ int   g_deg[N_NODES];
__device__ int   g_offs[N_NODES];
__device__ int   g_cursor[N_NODES];
__device__ int   g_part[SCAN_BLOCKS];
__device__ int   g_perm[PERM_CAP];
// transposed weights, bf16 hi/lo split: [mat 0..5][n*128+k]
__device__ __nv_bfloat16 g_wh[6 * 128 * 128];
__device__ __nv_bfloat16 g_wl[6 * 128 * 128];

// ===========================================================================
__device__ __forceinline__ float4 bf4_to_f4(uint2 u) {
    __nv_bfloat162 a = *reinterpret_cast<__nv_bfloat162*>(&u.x);
    __nv_bfloat162 b = *reinterpret_cast<__nv_bfloat162*>(&u.y);
    float2 fa = __bfloat1622float2(a);
    float2 fb = __bfloat1622float2(b);
    return make_float4(fa.x, fa.y, fb.x, fb.y);
}
__device__ __forceinline__ __nv_bfloat162 as_bf2(uint32_t u) {
    return *reinterpret_cast<__nv_bfloat162*>(&u);
}
__device__ __forceinline__ uint32_t pack_bf16(float a, float b) {
    __nv_bfloat16 ha = __float2bfloat16(a);
    __nv_bfloat16 hb = __float2bfloat16(b);
    return (uint32_t)__bfloat16_as_ushort(ha) |
           ((uint32_t)__bfloat16_as_ushort(hb) << 16);
}

// ===========================================================================
// setup: weight prep + x->bf16 + deg zero + pool zero + perm sentinel prefill,
// all in ONE launch via disjoint index ranges.
// ===========================================================================
#define SETUP_W    (6 * 16384)                       // 98304
#define SETUP_X    (N_NODES * D / 4)                 // 3200000 (float4 units)
#define SETUP_DEG  N_NODES
#define SETUP_PF   (PERM_CAP / 4)                    // int4 prefill units
#define SETUP_TOTAL (SETUP_W + SETUP_X + SETUP_DEG + D + SETUP_PF)

__global__ void setup_kernel(
    const float* __restrict__ W0, const float* __restrict__ W1,
    const float* __restrict__ W2, const float* __restrict__ W3,
    const float* __restrict__ W4, const float* __restrict__ W5,
    __nv_bfloat16* __restrict__ Th, __nv_bfloat16* __restrict__ Tl,
    const float4* __restrict__ x4, uint2* __restrict__ xb,
    int* __restrict__ deg, float* __restrict__ pool, int4* __restrict__ perm4)
{
    int t = blockIdx.x * 256 + threadIdx.x;
    if (t < SETUP_W) {
        int m = t >> 14, i = t & 16383;
        const float* W = (m == 0) ? W0 : (m == 1) ? W1 : (m == 2) ? W2
                       : (m == 3) ? W3 : (m == 4) ? W4 : W5;
        int n = i >> 7, k = i & 127;
        float w = W[k * 128 + n];
        __nv_bfloat16 h = __float2bfloat16(w);
        Th[t] = h;
        Tl[t] = __float2bfloat16(w - __bfloat162float(h));
    } else if (t < SETUP_W + SETUP_X) {
        int i = t - SETUP_W;
        float4 v = __ldg(x4 + i);
        uint2 o;
        o.x = pack_bf16(v.x, v.y);
        o.y = pack_bf16(v.z, v.w);
        xb[i] = o;
    } else if (t < SETUP_W + SETUP_X + SETUP_DEG) {
        deg[t - SETUP_W - SETUP_X] = 0;
    } else if (t < SETUP_W + SETUP_X + SETUP_DEG + D) {
        pool[t - SETUP_W - SETUP_X - SETUP_DEG] = 0.f;
    } else if (t < SETUP_TOTAL) {
        int i = t - SETUP_W - SETUP_X - SETUP_DEG - D;
        perm4[i] = make_int4(N_NODES, N_NODES, N_NODES, N_NODES);
    }
}

// ===========================================================================
// CSR build (8-padded segments)
// ===========================================================================
__global__ void count_kernel(const int4* __restrict__ dst4, int* __restrict__ deg) {
    int i = blockIdx.x * blockDim.x + threadIdx.x;
    if (i < N_EDGES / 4) {
        int4 d = __ldg(dst4 + i);
        atomicAdd(&deg[d.x], 1);
        atomicAdd(&deg[d.y], 1);
        atomicAdd(&deg[d.z], 1);
        atomicAdd(&deg[d.w], 1);
    }
}
// blockwise exclusive scan over PADDED counts ((deg+7)&~7)
__global__ void scan1_kernel(const int* __restrict__ deg,
                             int* __restrict__ offs, int* __restrict__ cursor,
                             int* __restrict__ part) {
    __shared__ int s[256];
    int t = threadIdx.x;
    int i = blockIdx.x * 256 + t;
    int v = (i < N_NODES) ? ((deg[i] + 7) & ~7) : 0;
    s[t] = v;
    __syncthreads();
#pragma unroll
    for (int d = 1; d < 256; d <<= 1) {
        int u = (t >= d) ? s[t - d] : 0;
        __syncthreads();
        s[t] += u;
        __syncthreads();
    }
    if (i < N_NODES) {
        int o = s[t] - v;
        offs[i] = o;
        cursor[i] = o;
    }
    if (t == 255) part[blockIdx.x] = s[255];
}
__global__ void scan2_kernel(int* __restrict__ part) {
    __shared__ int s[512];
    int t = threadIdx.x;
    int v = (t < SCAN_BLOCKS) ? part[t] : 0;
    s[t] = v;
    __syncthreads();
#pragma unroll
    for (int d = 1; d < 512; d <<= 1) {
        int u = (t >= d) ? s[t - d] : 0;
        __syncthreads();
        s[t] += u;
        __syncthreads();
    }
    if (t < SCAN_BLOCKS) part[t] = s[t] - v;
}
__global__ void permute_kernel(const int4* __restrict__ src4, const int4* __restrict__ dst4,
                               int* __restrict__ cursor, const int* __restrict__ part,
                               int* __restrict__ perm) {
    int i = blockIdx.x * blockDim.x + threadIdx.x;
    if (i < N_EDGES / 4) {
        int4 s = __ldg(src4 + i);
        int4 d = __ldg(dst4 + i);
        int p0 = atomicAdd(&cursor[d.x], 1) + __ldg(&part[d.x >> 8]);
        int p1 = atomicAdd(&cursor[d.y], 1) + __ldg(&part[d.y >> 8]);
        int p2 = atomicAdd(&cursor[d.z], 1) + __ldg(&part[d.z >> 8]);
        int p3 = atomicAdd(&cursor[d.w], 1) + __ldg(&part[d.w >> 8]);
        perm[p0] = s.x;
        perm[p1] = s.y;
        perm[p2] = s.z;
        perm[p3] = s.w;
    }
}

// ===========================================================================
// gather-based mean aggregation: one warp per node, exact 8-edge iterations
// (segments padded with sentinel N_NODES whose feature row is all zeros).
// 2 aligned int4 perm loads per iteration; HADD2 tree; fp32 partial accum.
// ===========================================================================
__global__ __launch_bounds__(256) void gather_aggr(
    const __nv_bfloat16* __restrict__ xv, const int* __restrict__ perm,
    const int* __restrict__ offs, const int* __restrict__ part,
    const int* __restrict__ deg, __nv_bfloat16* __restrict__ aggr)
{
    int warp = (blockIdx.x * blockDim.x + threadIdx.x) >> 5;
    int lane = threadIdx.x & 31;
    if (warp >= N_NODES) return;
    int beg = __ldg(&offs[warp]) + __ldg(&part[warp >> 8]);
    int cnt = __ldg(&deg[warp]);
    int pcnt = (cnt + 7) & ~7;

    const uint2* x2 = (const uint2*)xv;

    float4 acc = make_float4(0.f, 0.f, 0.f, 0.f);
    for (int e = beg; e < beg + pcnt; e += 8) {
        const int4* pp = (const int4*)(perm + e);    // 32B-aligned (beg%8==0)
        int4 a = __ldg(pp);
        int4 b = __ldg(pp + 1);
        uint2 u0 = __ldg(x2 + (size_t)a.x * 32 + lane);
        uint2 u1 = __ldg(x2 + (size_t)a.y * 32 + lane);
        uint2 u2 = __ldg(x2 + (size_t)a.z * 32 + lane);
        uint2 u3 = __ldg(x2 + (size_t)a.w * 32 + lane);
        uint2 u4 = __ldg(x2 + (size_t)b.x * 32 + lane);
        uint2 u5 = __ldg(x2 + (size_t)b.y * 32 + lane);
        uint2 u6 = __ldg(x2 + (size_t)b.z * 32 + lane);
        uint2 u7 = __ldg(x2 + (size_t)b.w * 32 + lane);
        __nv_bfloat162 px = __hadd2(
            __hadd2(__hadd2(as_bf2(u0.x), as_bf2(u1.x)),
                    __hadd2(as_bf2(u2.x), as_bf2(u3.x))),
            __hadd2(__hadd2(as_bf2(u4.x), as_bf2(u5.x)),
                    __hadd2(as_bf2(u6.x), as_bf2(u7.x))));
        __nv_bfloat162 py = __hadd2(
            __hadd2(__hadd2(as_bf2(u0.y), as_bf2(u1.y)),
                    __hadd2(as_bf2(u2.y), as_bf2(u3.y))),
            __hadd2(__hadd2(as_bf2(u4.y), as_bf2(u5.y)),
                    __hadd2(as_bf2(u6.y), as_bf2(u7.y))));
        float2 fx = __bfloat1622float2(px);
        float2 fy = __bfloat1622float2(py);
        acc.x += fx.x; acc.y += fx.y;
        acc.z += fy.x; acc.w += fy.y;
    }
    float sc = (cnt > 0) ? (1.0f / (float)cnt) : 0.0f;
    uint2 o;
    o.x = pack_bf16(acc.x * sc, acc.y * sc);
    o.y = pack_bf16(acc.z * sc, acc.w * sc);
    ((uint2*)aggr)[(size_t)warp * 32 + lane] = o;
}

// ===========================================================================
// bf16 mma.sync fused SAGE layer (R12 structure, static smem):
//   out_bf16 = relu( aggr @ Wl + xin @ Wr + b )
// A single bf16 (2 MMAs vs W hi/lo). CTA 128x128, warp 64x32, K=256 in 8x32.
// ===========================================================================
#define A_STRIDE 80   // 16B-aligned; bank = (grp*20 + tig) mod 32 -> conflict-free
#define TILE_BYTES (128 * A_STRIDE)  // 10240

__device__ __forceinline__ void mma_bf16(float* c, const uint32_t* a,
                                         uint32_t b0, uint32_t b1) {
    asm volatile(
        "mma.sync.aligned.m16n8k16.row.col.f32.bf16.bf16.f32 "
        "{%0,%1,%2,%3}, {%4,%5,%6,%7}, {%8,%9}, {%0,%1,%2,%3};\n"
        : "+f"(c[0]), "+f"(c[1]), "+f"(c[2]), "+f"(c[3])
        : "r"(a[0]), "r"(a[1]), "r"(a[2]), "r"(a[3]), "r"(b0), "r"(b1));
}

__global__ __launch_bounds__(256, 2) void sage_gemm_mma(
    const __nv_bfloat16* __restrict__ aggr, const __nv_bfloat16* __restrict__ xin,
    const __nv_bfloat16* __restrict__ WlTh, const __nv_bfloat16* __restrict__ WlTl,
    const __nv_bfloat16* __restrict__ WrTh, const __nv_bfloat16* __restrict__ WrTl,
    const float* __restrict__ bias, __nv_bfloat16* __restrict__ out)
{
    __shared__ char sAh[TILE_BYTES];
    __shared__ char sWh[TILE_BYTES];
    __shared__ char sWl[TILE_BYTES];

    const int t    = threadIdx.x;
    const int wid  = t >> 5;
    const int lane = t & 31;
    const int grp  = lane >> 2;
    const int tig  = lane & 3;
    const int warpM = wid >> 2;
    const int warpN = wid & 3;
    const int m0 = blockIdx.x * 128;

    float acc[4][4][4];
#pragma unroll
    for (int i = 0; i < 4; i++)
#pragma unroll
        for (int j = 0; j < 4; j++)
#pragma unroll
            for (int r = 0; r < 4; r++) acc[i][j][r] = 0.f;

    const int arow  = t >> 1;
    const int ahalf = t & 1;
    const int gr = m0 + arow;

    for (int c = 0; c < 8; c++) {
        const bool fh = (c < 4);          // aggregation half of K
        const int k0 = (c & 3) * 32;

        // ---- load A chunk (bf16 straight copy): rows 128 x 32 k
        {
            const __nv_bfloat16* srcb = fh ? aggr : xin;
            const uint4* srcp = (const uint4*)(srcb + (size_t)gr * 128 + k0 + ahalf * 16);
            uint4 v0 = make_uint4(0u, 0u, 0u, 0u);
            uint4 v1 = make_uint4(0u, 0u, 0u, 0u);
            if (gr < N_NODES) { v0 = __ldg(srcp); v1 = __ldg(srcp + 1); }
            char* row = sAh + arow * A_STRIDE + ahalf * 32;
            *((uint4*)(row + 0))  = v0;
            *((uint4*)(row + 16)) = v1;
        }
        // ---- load W chunk: 128 n-rows x 32 k bf16, hi (t<128) / lo (t>=128)
        {
            int n = t & 127;
            const __nv_bfloat16* wsrc =
                fh ? ((t < 128) ? WlTh : WlTl) : ((t < 128) ? WrTh : WrTl);
            char* wdst = (t < 128) ? sWh : sWl;
            const uint4* src16 = (const uint4*)(wsrc + n * 128 + k0);
            uint4 v0 = __ldg(src16 + 0);
            uint4 v1 = __ldg(src16 + 1);
            uint4 v2 = __ldg(src16 + 2);
            uint4 v3 = __ldg(src16 + 3);
            char* row = wdst + n * A_STRIDE;
            *((uint4*)(row + 0))  = v0;
            *((uint4*)(row + 16)) = v1;
            *((uint4*)(row + 32)) = v2;
            *((uint4*)(row + 48)) = v3;
        }
        __syncthreads();

        // ---- compute: 2 k16-steps
#pragma unroll
        for (int kk = 0; kk < 2; kk++) {
            const int kb = kk * 32;
            uint32_t ah[4][4];
#pragma unroll
            for (int mi = 0; mi < 4; mi++) {
                int rb = warpM * 64 + mi * 16;
                int r1 = (rb + grp) * A_STRIDE + kb + tig * 4;
                int r2 = (rb + grp + 8) * A_STRIDE + kb + tig * 4;
                ah[mi][0] = *((uint32_t*)(sAh + r1));
                ah[mi][1] = *((uint32_t*)(sAh + r2));
                ah[mi][2] = *((uint32_t*)(sAh + r1 + 16));
                ah[mi][3] = *((uint32_t*)(sAh + r2 + 16));
            }
#pragma unroll
            for (int ni = 0; ni < 4; ni++) {
                int nrow = warpN * 32 + ni * 8 + grp;
                int wo = nrow * A_STRIDE + kb + tig * 4;
                uint32_t wh0 = *((uint32_t*)(sWh + wo));
                uint32_t wh1 = *((uint32_t*)(sWh + wo + 16));
                uint32_t wl0 = *((uint32_t*)(sWl + wo));
                uint32_t wl1 = *((uint32_t*)(sWl + wo + 16));
#pragma unroll
                for (int mi = 0; mi < 4; mi++) {
                    mma_bf16(acc[mi][ni], ah[mi], wh0, wh1);
                    mma_bf16(acc[mi][ni], ah[mi], wl0, wl1);
                }
            }
        }
        __syncthreads();
    }

    // ---- epilogue: bias + relu, bf16 stores
#pragma unroll
    for (int mi = 0; mi < 4; mi++) {
        int r1 = m0 + warpM * 64 + mi * 16 + grp;
        int r2 = r1 + 8;
#pragma unroll
        for (int ni = 0; ni < 4; ni++) {
            int col = warpN * 32 + ni * 8 + tig * 2;
            float b0 = __ldg(&bias[col]);
            float b1 = __ldg(&bias[col + 1]);
            if (r1 < N_NODES) {
                __nv_bfloat162 v = __floats2bfloat162_rn(
                    fmaxf(acc[mi][ni][0] + b0, 0.f),
                    fmaxf(acc[mi][ni][1] + b1, 0.f));
                *((__nv_bfloat162*)(out + (size_t)r1 * 128 + col)) = v;
            }
            if (r2 < N_NODES) {
                __nv_bfloat162 v = __floats2bfloat162_rn(
                    fmaxf(acc[mi][ni][2] + b0, 0.f),
                    fmaxf(acc[mi][ni][3] + b1, 0.f));
                *((__nv_bfloat162*)(out + (size_t)r2 * 128 + col)) = v;
            }
        }
    }
}

// ===========================================================================
__global__ void pool_kernel(const __nv_bfloat16* __restrict__ h,
                            float* __restrict__ pool) {
    __shared__ float4 s[256];
    int t = threadIdx.x;
    int c = t & 31;
    int rlane = t >> 5;
    float4 acc = make_float4(0.f, 0.f, 0.f, 0.f);
    const uint2* h2 = (const uint2*)h;
    for (int r = blockIdx.x * 8 + rlane; r < N_NODES; r += gridDim.x * 8) {
        float4 v = bf4_to_f4(__ldg(h2 + (size_t)r * 32 + c));
        acc.x += v.x; acc.y += v.y; acc.z += v.z; acc.w += v.w;
    }
    s[t] = acc;
    __syncthreads();
    if (rlane == 0) {
#pragma unroll
        for (int i = 1; i < 8; i++) {
            float4 v = s[i * 32 + c];
            acc.x += v.x; acc.y += v.y; acc.z += v.z; acc.w += v.w;
        }
        atomicAdd(&pool[c * 4 + 0], acc.x);
        atomicAdd(&pool[c * 4 + 1], acc.y);
        atomicAdd(&pool[c * 4 + 2], acc.z);
        atomicAdd(&pool[c * 4 + 3], acc.w);
    }
}

__global__ void head_kernel(const float* __restrict__ pool,
                            const float* __restrict__ Wg,
                            const float* __restrict__ bg,
                            float* __restrict__ out) {
    int j = threadIdx.x;
    if (j >= D_LAT) return;
    float acc = bg[j];
    const float invn = 1.0f / (float)N_NODES;
#pragma unroll 8
    for (int k = 0; k < D; k++)
        acc += (pool[k] * invn) * Wg[k * D_LAT + j];
    out[j] = 1.0f / (1.0f + expf(-acc));
}

// ===========================================================================
extern "C" void kernel_launch(void* const* d_in, const int* in_sizes, int n_in,
                              void* d_out, int out_size) {
    const float* x   = (const float*)d_in[0];
    const int*   ei  = (const int*)d_in[1];
    const float* b1  = (const float*)d_in[4];
    const float* b2  = (const float*)d_in[7];
    const float* b3  = (const float*)d_in[10];
    const float* Wg  = (const float*)d_in[11];
    const float* bg  = (const float*)d_in[12];
    float* out = (float*)d_out;

    const int* src = ei;
    const int* dst = ei + N_EDGES;

    float *pool;
    __nv_bfloat16 *xbf, *aggr, *hA, *hB, *wh, *wl;
    int *deg, *offs, *cursor, *part, *perm;
    cudaGetSymbolAddress((void**)&xbf,    g_xbf);
    cudaGetSymbolAddress((void**)&aggr,   g_aggr);
    cudaGetSymbolAddress((void**)&hA,     g_hA);
    cudaGetSymbolAddress((void**)&hB,     g_hB);
    cudaGetSymbolAddress((void**)&pool,   g_pool);
    cudaGetSymbolAddress((void**)&deg,    g_deg);
    cudaGetSymbolAddress((void**)&offs,   g_offs);
    cudaGetSymbolAddress((void**)&cursor, g_cursor);
    cudaGetSymbolAddress((void**)&part,   g_part);
    cudaGetSymbolAddress((void**)&perm,   g_perm);
    cudaGetSymbolAddress((void**)&wh,     g_wh);
    cudaGetSymbolAddress((void**)&wl,     g_wl);

    const int gemm_blocks = (N_NODES + 127) / 128;      // 782
    const int aggr_blocks = (N_NODES + 7) / 8;          // 12500
    const int edge4_blocks = (N_EDGES / 4 + 255) / 256; // 1563

#define WTH(m) (wh + (size_t)(m) * 16384)
#define WTL(m) (wl + (size_t)(m) * 16384)

    // 1: setup (weight prep + x conversion + deg/pool zero + perm prefill)
    setup_kernel<<<(SETUP_TOTAL + 255) / 256, 256>>>(
        (const float*)d_in[2], (const float*)d_in[3],
        (const float*)d_in[5], (const float*)d_in[6],
        (const float*)d_in[8], (const float*)d_in[9],
        wh, wl, (const float4*)x, (uint2*)xbf, deg, pool, (int4*)perm);
    // 2-5: padded CSR build
    count_kernel<<<edge4_blocks, 256>>>((const int4*)dst, deg);
    scan1_kernel<<<SCAN_BLOCKS, 256>>>(deg, offs, cursor, part);
    scan2_kernel<<<1, 512>>>(part);
    permute_kernel<<<edge4_blocks, 256>>>((const int4*)src, (const int4*)dst,
                                          cursor, part, perm);

    // layer 1
    gather_aggr<<<aggr_blocks, 256>>>(xbf, perm, offs, part, deg, aggr);
    sage_gemm_mma<<<gemm_blocks, 256>>>(
        aggr, xbf, WTH(0), WTL(0), WTH(1), WTL(1), b1, hA);

    // layer 2
    gather_aggr<<<aggr_blocks, 256>>>(hA, perm, offs, part, deg, aggr);
    sage_gemm_mma<<<gemm_blocks, 256>>>(
        aggr, hA, WTH(2), WTL(2), WTH(3), WTL(3), b2, hB);

    // layer 3
    gather_aggr<<<aggr_blocks, 256>>>(hB, perm, offs, part, deg, aggr);
    sage_gemm_mma<<<gemm_blocks, 256>>>(
        aggr, hB, WTH(4), WTL(4), WTH(5), WTL(5), b3, hA);

    // pool + head
    pool_kernel<<<256, 256>>>(hA, pool);
    head_kernel<<<1, 64>>>(pool, Wg, bg, out);
}

// round 16
// speedup vs baseline: 1.1195x; 1.1195x over previous
#include <cuda_runtime.h>
#include <cuda_bf16.h>
#include <math.h>
#include <cstdint>

#define N_NODES 100000
#define D 128
#define D_LAT 64
#define N_EDGES 1600000
#define SCAN_BLOCKS ((N_NODES + 255) / 256)   // 391

// Scratch (device globals: allocation-free, graph-capture safe)
__device__ __nv_bfloat16  g_xbf[(size_t)N_NODES * D];
__device__ __nv_bfloat16  g_aggr[(size_t)N_NODES * D];
__device__ __nv_bfloat16  g_hA[(size_t)N_NODES * D];
__device__ __nv_bfloat16  g_hB[(size_t)N_NODES * D];
__device__ float g_pool[D];
__device__ int   g_deg[N_NODES];
__device__ int   g_offs[N_NODES];
__device__ int   g_cursor[N_NODES];
__device__ int   g_part[SCAN_BLOCKS];
__device__ int   g_perm[N_EDGES];
// transposed weights, bf16 hi/lo split: [mat 0..5][n*128+k]
__device__ __nv_bfloat16 g_wh[6 * 128 * 128];
__device__ __nv_bfloat16 g_wl[6 * 128 * 128];

// ===========================================================================
__device__ __forceinline__ float4 bf4_to_f4(uint2 u) {
    __nv_bfloat162 a = *reinterpret_cast<__nv_bfloat162*>(&u.x);
    __nv_bfloat162 b = *reinterpret_cast<__nv_bfloat162*>(&u.y);
    float2 fa = __bfloat1622float2(a);
    float2 fb = __bfloat1622float2(b);
    return make_float4(fa.x, fa.y, fb.x, fb.y);
}
__device__ __forceinline__ __nv_bfloat162 as_bf2(uint32_t u) {
    return *reinterpret_cast<__nv_bfloat162*>(&u);
}
__device__ __forceinline__ uint32_t pack_bf16(float a, float b) {
    __nv_bfloat16 ha = __float2bfloat16(a);
    __nv_bfloat16 hb = __float2bfloat16(b);
    return (uint32_t)__bfloat16_as_ushort(ha) |
           ((uint32_t)__bfloat16_as_ushort(hb) << 16);
}

// ===========================================================================
// setup: weight prep (6 mats) + x->bf16 conversion + deg zero + pool zero,
// all in ONE launch via disjoint index ranges.
// ===========================================================================
#define SETUP_W    (6 * 16384)                       // 98304
#define SETUP_X    (N_NODES * D / 4)                 // 3200000 (float4 units)
#define SETUP_DEG  N_NODES
#define SETUP_TOTAL (SETUP_W + SETUP_X + SETUP_DEG + D)

__global__ void setup_kernel(
    const float* __restrict__ W0, const float* __restrict__ W1,
    const float* __restrict__ W2, const float* __restrict__ W3,
    const float* __restrict__ W4, const float* __restrict__ W5,
    __nv_bfloat16* __restrict__ Th, __nv_bfloat16* __restrict__ Tl,
    const float4* __restrict__ x4, uint2* __restrict__ xb,
    int* __restrict__ deg, float* __restrict__ pool)
{
    int t = blockIdx.x * 256 + threadIdx.x;
    if (t < SETUP_W) {
        int m = t >> 14, i = t & 16383;
        const float* W = (m == 0) ? W0 : (m == 1) ? W1 : (m == 2) ? W2
                       : (m == 3) ? W3 : (m == 4) ? W4 : W5;
        int n = i >> 7, k = i & 127;
        float w = W[k * 128 + n];
        __nv_bfloat16 h = __float2bfloat16(w);
        Th[t] = h;
        Tl[t] = __float2bfloat16(w - __bfloat162float(h));
    } else if (t < SETUP_W + SETUP_X) {
        int i = t - SETUP_W;
        float4 v = __ldg(x4 + i);
        uint2 o;
        o.x = pack_bf16(v.x, v.y);
        o.y = pack_bf16(v.z, v.w);
        xb[i] = o;
    } else if (t < SETUP_W + SETUP_X + SETUP_DEG) {
        deg[t - SETUP_W - SETUP_X] = 0;
    } else if (t < SETUP_TOTAL) {
        pool[t - SETUP_W - SETUP_X - SETUP_DEG] = 0.f;
    }
}

// ===========================================================================
// CSR build
// ===========================================================================
__global__ void count_kernel(const int4* __restrict__ dst4, int* __restrict__ deg) {
    int i = blockIdx.x * blockDim.x + threadIdx.x;
    if (i < N_EDGES / 4) {
        int4 d = __ldg(dst4 + i);
        atomicAdd(&deg[d.x], 1);
        atomicAdd(&deg[d.y], 1);
        atomicAdd(&deg[d.z], 1);
        atomicAdd(&deg[d.w], 1);
    }
}
__global__ void scan1_kernel(const int* __restrict__ deg,
                             int* __restrict__ offs, int* __restrict__ cursor,
                             int* __restrict__ part) {
    __shared__ int s[256];
    int t = threadIdx.x;
    int i = blockIdx.x * 256 + t;
    int v = (i < N_NODES) ? deg[i] : 0;
    s[t] = v;
    __syncthreads();
#pragma unroll
    for (int d = 1; d < 256; d <<= 1) {
        int u = (t >= d) ? s[t - d] : 0;
        __syncthreads();
        s[t] += u;
        __syncthreads();
    }
    if (i < N_NODES) {
        int o = s[t] - v;     // blockwise exclusive
        offs[i] = o;
        cursor[i] = o;
    }
    if (t == 255) part[blockIdx.x] = s[255];
}
__global__ void scan2_kernel(int* __restrict__ part) {
    __shared__ int s[512];
    int t = threadIdx.x;
    int v = (t < SCAN_BLOCKS) ? part[t] : 0;
    s[t] = v;
    __syncthreads();
#pragma unroll
    for (int d = 1; d < 512; d <<= 1) {
        int u = (t >= d) ? s[t - d] : 0;
        __syncthreads();
        s[t] += u;
        __syncthreads();
    }
    if (t < SCAN_BLOCKS) part[t] = s[t] - v;
}
__global__ void permute_kernel(const int4* __restrict__ src4, const int4* __restrict__ dst4,
                               int* __restrict__ cursor, const int* __restrict__ part,
                               int* __restrict__ perm) {
    int i = blockIdx.x * blockDim.x + threadIdx.x;
    if (i < N_EDGES / 4) {
        int4 s = __ldg(src4 + i);
        int4 d = __ldg(dst4 + i);
        int p0 = atomicAdd(&cursor[d.x], 1) + __ldg(&part[d.x >> 8]);
        int p1 = atomicAdd(&cursor[d.y], 1) + __ldg(&part[d.y >> 8]);
        int p2 = atomicAdd(&cursor[d.z], 1) + __ldg(&part[d.z >> 8]);
        int p3 = atomicAdd(&cursor[d.w], 1) + __ldg(&part[d.w >> 8]);
        perm[p0] = s.x;
        perm[p1] = s.y;
        perm[p2] = s.z;
        perm[p3] = s.w;
    }
}

// ===========================================================================
// gather-based mean aggregation: one warp per node, unroll 8,
// pairwise HADD2 tree over the 8 rows, fp32 accumulation of partials.
// ===========================================================================
__global__ __launch_bounds__(256) void gather_aggr(
    const __nv_bfloat16* __restrict__ xv, const int* __restrict__ perm,
    const int* __restrict__ offs, const int* __restrict__ part,
    const int* __restrict__ deg, __nv_bfloat16* __restrict__ aggr)
{
    int warp = (blockIdx.x * blockDim.x + threadIdx.x) >> 5;
    int lane = threadIdx.x & 31;
    if (warp >= N_NODES) return;
    int beg = __ldg(&offs[warp]) + __ldg(&part[warp >> 8]);
    int cnt = __ldg(&deg[warp]);
    int end = beg + cnt;

    const uint2* x2 = (const uint2*)xv;

    float4 acc = make_float4(0.f, 0.f, 0.f, 0.f);
    int e = beg;
    for (; e + 8 <= end; e += 8) {
        int s0 = __ldg(&perm[e + 0]);
        int s1 = __ldg(&perm[e + 1]);
        int s2 = __ldg(&perm[e + 2]);
        int s3 = __ldg(&perm[e + 3]);
        int s4 = __ldg(&perm[e + 4]);
        int s5 = __ldg(&perm[e + 5]);
        int s6 = __ldg(&perm[e + 6]);
        int s7 = __ldg(&perm[e + 7]);
        uint2 u0 = __ldg(x2 + (size_t)s0 * 32 + lane);
        uint2 u1 = __ldg(x2 + (size_t)s1 * 32 + lane);
        uint2 u2 = __ldg(x2 + (size_t)s2 * 32 + lane);
        uint2 u3 = __ldg(x2 + (size_t)s3 * 32 + lane);
        uint2 u4 = __ldg(x2 + (size_t)s4 * 32 + lane);
        uint2 u5 = __ldg(x2 + (size_t)s5 * 32 + lane);
        uint2 u6 = __ldg(x2 + (size_t)s6 * 32 + lane);
        uint2 u7 = __ldg(x2 + (size_t)s7 * 32 + lane);
        __nv_bfloat162 px = __hadd2(
            __hadd2(__hadd2(as_bf2(u0.x), as_bf2(u1.x)),
                    __hadd2(as_bf2(u2.x), as_bf2(u3.x))),
            __hadd2(__hadd2(as_bf2(u4.x), as_bf2(u5.x)),
                    __hadd2(as_bf2(u6.x), as_bf2(u7.x))));
        __nv_bfloat162 py = __hadd2(
            __hadd2(__hadd2(as_bf2(u0.y), as_bf2(u1.y)),
                    __hadd2(as_bf2(u2.y), as_bf2(u3.y))),
            __hadd2(__hadd2(as_bf2(u4.y), as_bf2(u5.y)),
                    __hadd2(as_bf2(u6.y), as_bf2(u7.y))));
        float2 fx = __bfloat1622float2(px);
        float2 fy = __bfloat1622float2(py);
        acc.x += fx.x; acc.y += fx.y;
        acc.z += fy.x; acc.w += fy.y;
    }
    for (; e < end; e++) {
        int s0 = __ldg(&perm[e]);
        float4 v0 = bf4_to_f4(__ldg(x2 + (size_t)s0 * 32 + lane));
        acc.x += v0.x; acc.y += v0.y; acc.z += v0.z; acc.w += v0.w;
    }
    float sc = (cnt > 0) ? (1.0f / (float)cnt) : 0.0f;
    uint2 o;
    o.x = pack_bf16(acc.x * sc, acc.y * sc);
    o.y = pack_bf16(acc.z * sc, acc.w * sc);
    ((uint2*)aggr)[(size_t)warp * 32 + lane] = o;
}

// ===========================================================================
// bf16 mma.sync fused SAGE layer:
//   out_bf16 = relu( aggr @ Wl + xin @ Wr + b )
// A single bf16 (2 MMAs vs W hi/lo). CTA 128x128, warp 64x32, K=256 in 8x32.
// POOL=true (layer 3): also accumulates column sums into global pool[]
// (fused global mean pool; shfl + smem + global-atomic reduction).
// ===========================================================================
#define A_STRIDE 80   // 16B-aligned; bank = (grp*20 + tig) mod 32 -> conflict-free
#define TILE_BYTES (128 * A_STRIDE)  // 10240

__device__ __forceinline__ void mma_bf16(float* c, const uint32_t* a,
                                         uint32_t b0, uint32_t b1) {
    asm volatile(
        "mma.sync.aligned.m16n8k16.row.col.f32.bf16.bf16.f32 "
        "{%0,%1,%2,%3}, {%4,%5,%6,%7}, {%8,%9}, {%0,%1,%2,%3};\n"
        : "+f"(c[0]), "+f"(c[1]), "+f"(c[2]), "+f"(c[3])
        : "r"(a[0]), "r"(a[1]), "r"(a[2]), "r"(a[3]), "r"(b0), "r"(b1));
}

template<bool POOL>
__global__ __launch_bounds__(256, 2) void sage_gemm_mma_t(
    const __nv_bfloat16* __restrict__ aggr, const __nv_bfloat16* __restrict__ xin,
    const __nv_bfloat16* __restrict__ WlTh, const __nv_bfloat16* __restrict__ WlTl,
    const __nv_bfloat16* __restrict__ WrTh, const __nv_bfloat16* __restrict__ WrTl,
    const float* __restrict__ bias, __nv_bfloat16* __restrict__ out,
    float* __restrict__ pool)
{
    __shared__ char sAh[TILE_BYTES];
    __shared__ char sWh[TILE_BYTES];
    __shared__ char sWl[TILE_BYTES];
    __shared__ float spool[128];

    const int t    = threadIdx.x;
    const int wid  = t >> 5;
    const int lane = t & 31;
    const int grp  = lane >> 2;
    const int tig  = lane & 3;
    const int warpM = wid >> 2;
    const int warpN = wid & 3;
    const int m0 = blockIdx.x * 128;

    float acc[4][4][4];
#pragma unroll
    for (int i = 0; i < 4; i++)
#pragma unroll
        for (int j = 0; j < 4; j++)
#pragma unroll
            for (int r = 0; r < 4; r++) acc[i][j][r] = 0.f;

    const int arow  = t >> 1;
    const int ahalf = t & 1;
    const int gr = m0 + arow;

    for (int c = 0; c < 8; c++) {
        const bool fh = (c < 4);          // aggregation half of K
        const int k0 = (c & 3) * 32;

        // ---- load A chunk (bf16 straight copy): rows 128 x 32 k
        {
            const __nv_bfloat16* srcb = fh ? aggr : xin;
            const uint4* srcp = (const uint4*)(srcb + (size_t)gr * 128 + k0 + ahalf * 16);
            uint4 v0 = make_uint4(0u, 0u, 0u, 0u);
            uint4 v1 = make_uint4(0u, 0u, 0u, 0u);
            if (gr < N_NODES) { v0 = __ldg(srcp); v1 = __ldg(srcp + 1); }
            char* row = sAh + arow * A_STRIDE + ahalf * 32;
            *((uint4*)(row + 0))  = v0;
            *((uint4*)(row + 16)) = v1;
        }
        // ---- load W chunk: 128 n-rows x 32 k bf16, hi (t<128) / lo (t>=128)
        {
            int n = t & 127;
            const __nv_bfloat16* wsrc =
                fh ? ((t < 128) ? WlTh : WlTl) : ((t < 128) ? WrTh : WrTl);
            char* wdst = (t < 128) ? sWh : sWl;
            const uint4* src16 = (const uint4*)(wsrc + n * 128 + k0);
            uint4 v0 = __ldg(src16 + 0);
            uint4 v1 = __ldg(src16 + 1);
            uint4 v2 = __ldg(src16 + 2);
            uint4 v3 = __ldg(src16 + 3);
            char* row = wdst + n * A_STRIDE;
            *((uint4*)(row + 0))  = v0;
            *((uint4*)(row + 16)) = v1;
            *((uint4*)(row + 32)) = v2;
            *((uint4*)(row + 48)) = v3;
        }
        __syncthreads();

        // ---- compute: 2 k16-steps
#pragma unroll
        for (int kk = 0; kk < 2; kk++) {
            const int kb = kk * 32;
            uint32_t ah[4][4];
#pragma unroll
            for (int mi = 0; mi < 4; mi++) {
                int rb = warpM * 64 + mi * 16;
                int r1 = (rb + grp) * A_STRIDE + kb + tig * 4;
                int r2 = (rb + grp + 8) * A_STRIDE + kb + tig * 4;
                ah[mi][0] = *((uint32_t*)(sAh + r1));
                ah[mi][1] = *((uint32_t*)(sAh + r2));
                ah[mi][2] = *((uint32_t*)(sAh + r1 + 16));
                ah[mi][3] = *((uint32_t*)(sAh + r2 + 16));
            }
#pragma unroll
            for (int ni = 0; ni < 4; ni++) {
                int nrow = warpN * 32 + ni * 8 + grp;
                int wo = nrow * A_STRIDE + kb + tig * 4;
                uint32_t wh0 = *((uint32_t*)(sWh + wo));
                uint32_t wh1 = *((uint32_t*)(sWh + wo + 16));
                uint32_t wl0 = *((uint32_t*)(sWl + wo));
                uint32_t wl1 = *((uint32_t*)(sWl + wo + 16));
#pragma unroll
                for (int mi = 0; mi < 4; mi++) {
                    mma_bf16(acc[mi][ni], ah[mi], wh0, wh1);
                    mma_bf16(acc[mi][ni], ah[mi], wl0, wl1);
                }
            }
        }
        __syncthreads();
    }

    if (POOL) {
        if (t < 128) spool[t] = 0.f;
        __syncthreads();
    }

    // ---- epilogue: bias + relu, bf16 stores (+ optional pool partials)
    float2 psum[4];
    if (POOL)
#pragma unroll
        for (int ni = 0; ni < 4; ni++) psum[ni] = make_float2(0.f, 0.f);

#pragma unroll
    for (int mi = 0; mi < 4; mi++) {
        int r1 = m0 + warpM * 64 + mi * 16 + grp;
        int r2 = r1 + 8;
#pragma unroll
        for (int ni = 0; ni < 4; ni++) {
            int col = warpN * 32 + ni * 8 + tig * 2;
            float b0 = __ldg(&bias[col]);
            float b1 = __ldg(&bias[col + 1]);
            if (r1 < N_NODES) {
                float f0 = fmaxf(acc[mi][ni][0] + b0, 0.f);
                float f1 = fmaxf(acc[mi][ni][1] + b1, 0.f);
                *((__nv_bfloat162*)(out + (size_t)r1 * 128 + col)) =
                    __floats2bfloat162_rn(f0, f1);
                if (POOL) { psum[ni].x += f0; psum[ni].y += f1; }
            }
            if (r2 < N_NODES) {
                float f2 = fmaxf(acc[mi][ni][2] + b0, 0.f);
                float f3 = fmaxf(acc[mi][ni][3] + b1, 0.f);
                *((__nv_bfloat162*)(out + (size_t)r2 * 128 + col)) =
                    __floats2bfloat162_rn(f2, f3);
                if (POOL) { psum[ni].x += f2; psum[ni].y += f3; }
            }
        }
    }

    if (POOL) {
        // reduce across grp lanes (lane = grp*4 + tig): xor over bits 2..4
#pragma unroll
        for (int ni = 0; ni < 4; ni++) {
#pragma unroll
            for (int off = 4; off < 32; off <<= 1) {
                psum[ni].x += __shfl_xor_sync(0xffffffffu, psum[ni].x, off);
                psum[ni].y += __shfl_xor_sync(0xffffffffu, psum[ni].y, off);
            }
        }
        if (grp == 0) {
#pragma unroll
            for (int ni = 0; ni < 4; ni++) {
                int col = warpN * 32 + ni * 8 + tig * 2;
                atomicAdd(&spool[col],     psum[ni].x);
                atomicAdd(&spool[col + 1], psum[ni].y);
            }
        }
        __syncthreads();
        if (t < 128) atomicAdd(&pool[t], spool[t]);
    }
}

// ===========================================================================
__global__ void head_kernel(const float* __restrict__ pool,
                            const float* __restrict__ Wg,
                            const float* __restrict__ bg,
                            float* __restrict__ out) {
    int j = threadIdx.x;
    if (j >= D_LAT) return;
    float acc = bg[j];
    const float invn = 1.0f / (float)N_NODES;
#pragma unroll 8
    for (int k = 0; k < D; k++)
        acc += (pool[k] * invn) * Wg[k * D_LAT + j];
    out[j] = 1.0f / (1.0f + expf(-acc));
}

// ===========================================================================
extern "C" void kernel_launch(void* const* d_in, const int* in_sizes, int n_in,
                              void* d_out, int out_size) {
    const float* x   = (const float*)d_in[0];
    const int*   ei  = (const int*)d_in[1];
    const float* b1  = (const float*)d_in[4];
    const float* b2  = (const float*)d_in[7];
    const float* b3  = (const float*)d_in[10];
    const float* Wg  = (const float*)d_in[11];
    const float* bg  = (const float*)d_in[12];
    float* out = (float*)d_out;

    const int* src = ei;
    const int* dst = ei + N_EDGES;

    float *pool;
    __nv_bfloat16 *xbf, *aggr, *hA, *hB, *wh, *wl;
    int *deg, *offs, *cursor, *part, *perm;
    cudaGetSymbolAddress((void**)&xbf,    g_xbf);
    cudaGetSymbolAddress((void**)&aggr,   g_aggr);
    cudaGetSymbolAddress((void**)&hA,     g_hA);
    cudaGetSymbolAddress((void**)&hB,     g_hB);
    cudaGetSymbolAddress((void**)&pool,   g_pool);
    cudaGetSymbolAddress((void**)&deg,    g_deg);
    cudaGetSymbolAddress((void**)&offs,   g_offs);
    cudaGetSymbolAddress((void**)&cursor, g_cursor);
    cudaGetSymbolAddress((void**)&part,   g_part);
    cudaGetSymbolAddress((void**)&perm,   g_perm);
    cudaGetSymbolAddress((void**)&wh,     g_wh);
    cudaGetSymbolAddress((void**)&wl,     g_wl);

    const int gemm_blocks = (N_NODES + 127) / 128;      // 782
    const int aggr_blocks = (N_NODES + 7) / 8;          // 12500
    const int edge4_blocks = (N_EDGES / 4 + 255) / 256; // 1563

#define WTH(m) (wh + (size_t)(m) * 16384)
#define WTL(m) (wl + (size_t)(m) * 16384)

    // 1: setup (weight prep + x conversion + deg/pool zero)
    setup_kernel<<<(SETUP_TOTAL + 255) / 256, 256>>>(
        (const float*)d_in[2], (const float*)d_in[3],
        (const float*)d_in[5], (const float*)d_in[6],
        (const float*)d_in[8], (const float*)d_in[9],
        wh, wl, (const float4*)x, (uint2*)xbf, deg, pool);
    // 2-5: CSR build
    count_kernel<<<edge4_blocks, 256>>>((const int4*)dst, deg);
    scan1_kernel<<<SCAN_BLOCKS, 256>>>(deg, offs, cursor, part);
    scan2_kernel<<<1, 512>>>(part);
    permute_kernel<<<edge4_blocks, 256>>>((const int4*)src, (const int4*)dst,
                                          cursor, part, perm);

    // layer 1
    gather_aggr<<<aggr_blocks, 256>>>(xbf, perm, offs, part, deg, aggr);
    sage_gemm_mma_t<false><<<gemm_blocks, 256>>>(
        aggr, xbf, WTH(0), WTL(0), WTH(1), WTL(1), b1, hA, pool);

    // layer 2
    gather_aggr<<<aggr_blocks, 256>>>(hA, perm, offs, part, deg, aggr);
    sage_gemm_mma_t<false><<<gemm_blocks, 256>>>(
        aggr, hA, WTH(2), WTL(2), WTH(3), WTL(3), b2, hB, pool);

    // layer 3 (pool fused into epilogue)
    gather_aggr<<<aggr_blocks, 256>>>(hB, perm, offs, part, deg, aggr);
    sage_gemm_mma_t<true><<<gemm_blocks, 256>>>(
        aggr, hB, WTH(4), WTL(4), WTH(5), WTL(5), b3, hA, pool);

    // head
    head_kernel<<<1, 64>>>(pool, Wg, bg, out);
}

// round 17
// speedup vs baseline: 1.1321x; 1.0112x over previous
#include <cuda_runtime.h>
#include <cuda_bf16.h>
#include <math.h>
#include <cstdint>

#define N_NODES 100000
#define D 128
#define D_LAT 64
#define N_EDGES 1600000
#define SCAN_BLOCKS ((N_NODES + 255) / 256)   // 391

// Scratch (device globals: allocation-free, graph-capture safe)
__device__ __nv_bfloat16  g_xbf[(size_t)N_NODES * D];
__device__ __nv_bfloat16  g_aggr[(size_t)N_NODES * D];
__device__ __nv_bfloat16  g_hA[(size_t)N_NODES * D];
__device__ __nv_bfloat16  g_hB[(size_t)N_NODES * D];
__device__ float g_pool[D];
__device__ int   g_deg[N_NODES];
__device__ int   g_offs[N_NODES];
__device__ int   g_cursor[N_NODES];
__device__ int   g_part[SCAN_BLOCKS];
__device__ int   g_perm[N_EDGES];
// transposed weights, bf16 hi/lo split: [mat 0..5][n*128+k]
__device__ __nv_bfloat16 g_wh[6 * 128 * 128];
__device__ __nv_bfloat16 g_wl[6 * 128 * 128];

// ===========================================================================
__device__ __forceinline__ float4 bf4_to_f4(uint2 u) {
    __nv_bfloat162 a = *reinterpret_cast<__nv_bfloat162*>(&u.x);
    __nv_bfloat162 b = *reinterpret_cast<__nv_bfloat162*>(&u.y);
    float2 fa = __bfloat1622float2(a);
    float2 fb = __bfloat1622float2(b);
    return make_float4(fa.x, fa.y, fb.x, fb.y);
}
__device__ __forceinline__ __nv_bfloat162 as_bf2(uint32_t u) {
    return *reinterpret_cast<__nv_bfloat162*>(&u);
}
__device__ __forceinline__ uint32_t pack_bf16(float a, float b) {
    __nv_bfloat16 ha = __float2bfloat16(a);
    __nv_bfloat16 hb = __float2bfloat16(b);
    return (uint32_t)__bfloat16_as_ushort(ha) |
           ((uint32_t)__bfloat16_as_ushort(hb) << 16);
}

// ===========================================================================
// setup: weight prep (6 mats) + x->bf16 conversion + deg zero + pool zero,
// all in ONE launch via disjoint index ranges.
// ===========================================================================
#define SETUP_W    (6 * 16384)                       // 98304
#define SETUP_X    (N_NODES * D / 4)                 // 3200000 (float4 units)
#define SETUP_DEG  N_NODES
#define SETUP_TOTAL (SETUP_W + SETUP_X + SETUP_DEG + D)

__global__ void setup_kernel(
    const float* __restrict__ W0, const float* __restrict__ W1,
    const float* __restrict__ W2, const float* __restrict__ W3,
    const float* __restrict__ W4, const float* __restrict__ W5,
    __nv_bfloat16* __restrict__ Th, __nv_bfloat16* __restrict__ Tl,
    const float4* __restrict__ x4, uint2* __restrict__ xb,
    int* __restrict__ deg, float* __restrict__ pool)
{
    int t = blockIdx.x * 256 + threadIdx.x;
    if (t < SETUP_W) {
        int m = t >> 14, i = t & 16383;
        const float* W = (m == 0) ? W0 : (m == 1) ? W1 : (m == 2) ? W2
                       : (m == 3) ? W3 : (m == 4) ? W4 : W5;
        int n = i >> 7, k = i & 127;
        float w = W[k * 128 + n];
        __nv_bfloat16 h = __float2bfloat16(w);
        Th[t] = h;
        Tl[t] = __float2bfloat16(w - __bfloat162float(h));
    } else if (t < SETUP_W + SETUP_X) {
        int i = t - SETUP_W;
        float4 v = __ldg(x4 + i);
        uint2 o;
        o.x = pack_bf16(v.x, v.y);
        o.y = pack_bf16(v.z, v.w);
        xb[i] = o;
    } else if (t < SETUP_W + SETUP_X + SETUP_DEG) {
        deg[t - SETUP_W - SETUP_X] = 0;
    } else if (t < SETUP_TOTAL) {
        pool[t - SETUP_W - SETUP_X - SETUP_DEG] = 0.f;
    }
}

// ===========================================================================
// CSR build
// ===========================================================================
__global__ void count_kernel(const int4* __restrict__ dst4, int* __restrict__ deg) {
    int i = blockIdx.x * blockDim.x + threadIdx.x;
    if (i < N_EDGES / 4) {
        int4 d = __ldg(dst4 + i);
        atomicAdd(&deg[d.x], 1);
        atomicAdd(&deg[d.y], 1);
        atomicAdd(&deg[d.z], 1);
        atomicAdd(&deg[d.w], 1);
    }
}
__global__ void scan1_kernel(const int* __restrict__ deg,
                             int* __restrict__ offs, int* __restrict__ cursor,
                             int* __restrict__ part) {
    __shared__ int s[256];
    int t = threadIdx.x;
    int i = blockIdx.x * 256 + t;
    int v = (i < N_NODES) ? deg[i] : 0;
    s[t] = v;
    __syncthreads();
#pragma unroll
    for (int d = 1; d < 256; d <<= 1) {
        int u = (t >= d) ? s[t - d] : 0;
        __syncthreads();
        s[t] += u;
        __syncthreads();
    }
    if (i < N_NODES) {
        int o = s[t] - v;     // blockwise exclusive
        offs[i] = o;
        cursor[i] = o;
    }
    if (t == 255) part[blockIdx.x] = s[255];
}
__global__ void scan2_kernel(int* __restrict__ part) {
    __shared__ int s[512];
    int t = threadIdx.x;
    int v = (t < SCAN_BLOCKS) ? part[t] : 0;
    s[t] = v;
    __syncthreads();
#pragma unroll
    for (int d = 1; d < 512; d <<= 1) {
        int u = (t >= d) ? s[t - d] : 0;
        __syncthreads();
        s[t] += u;
        __syncthreads();
    }
    if (t < SCAN_BLOCKS) part[t] = s[t] - v;
}
__global__ void permute_kernel(const int4* __restrict__ src4, const int4* __restrict__ dst4,
                               int* __restrict__ cursor, const int* __restrict__ part,
                               int* __restrict__ perm) {
    int i = blockIdx.x * blockDim.x + threadIdx.x;
    if (i < N_EDGES / 4) {
        int4 s = __ldg(src4 + i);
        int4 d = __ldg(dst4 + i);
        int p0 = atomicAdd(&cursor[d.x], 1) + __ldg(&part[d.x >> 8]);
        int p1 = atomicAdd(&cursor[d.y], 1) + __ldg(&part[d.y >> 8]);
        int p2 = atomicAdd(&cursor[d.z], 1) + __ldg(&part[d.z >> 8]);
        int p3 = atomicAdd(&cursor[d.w], 1) + __ldg(&part[d.w >> 8]);
        perm[p0] = s.x;
        perm[p1] = s.y;
        perm[p2] = s.z;
        perm[p3] = s.w;
    }
}

// ===========================================================================
// gather-based mean aggregation: one warp per node, unroll 8,
// pairwise HADD2 tree over the 8 rows, fp32 accumulation of partials.
// ===========================================================================
__global__ __launch_bounds__(256) void gather_aggr(
    const __nv_bfloat16* __restrict__ xv, const int* __restrict__ perm,
    const int* __restrict__ offs, const int* __restrict__ part,
    const int* __restrict__ deg, __nv_bfloat16* __restrict__ aggr)
{
    int warp = (blockIdx.x * blockDim.x + threadIdx.x) >> 5;
    int lane = threadIdx.x & 31;
    if (warp >= N_NODES) return;
    int beg = __ldg(&offs[warp]) + __ldg(&part[warp >> 8]);
    int cnt = __ldg(&deg[warp]);
    int end = beg + cnt;

    const uint2* x2 = (const uint2*)xv;

    float4 acc = make_float4(0.f, 0.f, 0.f, 0.f);
    int e = beg;
    for (; e + 8 <= end; e += 8) {
        int s0 = __ldg(&perm[e + 0]);
        int s1 = __ldg(&perm[e + 1]);
        int s2 = __ldg(&perm[e + 2]);
        int s3 = __ldg(&perm[e + 3]);
        int s4 = __ldg(&perm[e + 4]);
        int s5 = __ldg(&perm[e + 5]);
        int s6 = __ldg(&perm[e + 6]);
        int s7 = __ldg(&perm[e + 7]);
        uint2 u0 = __ldg(x2 + (size_t)s0 * 32 + lane);
        uint2 u1 = __ldg(x2 + (size_t)s1 * 32 + lane);
        uint2 u2 = __ldg(x2 + (size_t)s2 * 32 + lane);
        uint2 u3 = __ldg(x2 + (size_t)s3 * 32 + lane);
        uint2 u4 = __ldg(x2 + (size_t)s4 * 32 + lane);
        uint2 u5 = __ldg(x2 + (size_t)s5 * 32 + lane);
        uint2 u6 = __ldg(x2 + (size_t)s6 * 32 + lane);
        uint2 u7 = __ldg(x2 + (size_t)s7 * 32 + lane);
        __nv_bfloat162 px = __hadd2(
            __hadd2(__hadd2(as_bf2(u0.x), as_bf2(u1.x)),
                    __hadd2(as_bf2(u2.x), as_bf2(u3.x))),
            __hadd2(__hadd2(as_bf2(u4.x), as_bf2(u5.x)),
                    __hadd2(as_bf2(u6.x), as_bf2(u7.x))));
        __nv_bfloat162 py = __hadd2(
            __hadd2(__hadd2(as_bf2(u0.y), as_bf2(u1.y)),
                    __hadd2(as_bf2(u2.y), as_bf2(u3.y))),
            __hadd2(__hadd2(as_bf2(u4.y), as_bf2(u5.y)),
                    __hadd2(as_bf2(u6.y), as_bf2(u7.y))));
        float2 fx = __bfloat1622float2(px);
        float2 fy = __bfloat1622float2(py);
        acc.x += fx.x; acc.y += fx.y;
        acc.z += fy.x; acc.w += fy.y;
    }
    for (; e < end; e++) {
        int s0 = __ldg(&perm[e]);
        float4 v0 = bf4_to_f4(__ldg(x2 + (size_t)s0 * 32 + lane));
        acc.x += v0.x; acc.y += v0.y; acc.z += v0.z; acc.w += v0.w;
    }
    float sc = (cnt > 0) ? (1.0f / (float)cnt) : 0.0f;
    uint2 o;
    o.x = pack_bf16(acc.x * sc, acc.y * sc);
    o.y = pack_bf16(acc.z * sc, acc.w * sc);
    ((uint2*)aggr)[(size_t)warp * 32 + lane] = o;
}

// ===========================================================================
// bf16 mma.sync fused SAGE layer:
//   out_bf16 = relu( aggr @ Wl + xin @ Wr + b )
// A single bf16 (2 MMAs vs W hi/lo). CTA 128x128, warp 64x32, K=256 in 8x32.
// POOL=true (layer 3): output features are DEAD (only pool is consumed by the
// head) -> skip all global stores; compute bias+relu in registers and
// accumulate column sums into pool[] (shfl + smem + global atomics).
// ===========================================================================
#define A_STRIDE 80   // 16B-aligned; bank = (grp*20 + tig) mod 32 -> conflict-free
#define TILE_BYTES (128 * A_STRIDE)  // 10240

__device__ __forceinline__ void mma_bf16(float* c, const uint32_t* a,
                                         uint32_t b0, uint32_t b1) {
    asm volatile(
        "mma.sync.aligned.m16n8k16.row.col.f32.bf16.bf16.f32 "
        "{%0,%1,%2,%3}, {%4,%5,%6,%7}, {%8,%9}, {%0,%1,%2,%3};\n"
        : "+f"(c[0]), "+f"(c[1]), "+f"(c[2]), "+f"(c[3])
        : "r"(a[0]), "r"(a[1]), "r"(a[2]), "r"(a[3]), "r"(b0), "r"(b1));
}

template<bool POOL>
__global__ __launch_bounds__(256, 2) void sage_gemm_mma_t(
    const __nv_bfloat16* __restrict__ aggr, const __nv_bfloat16* __restrict__ xin,
    const __nv_bfloat16* __restrict__ WlTh, const __nv_bfloat16* __restrict__ WlTl,
    const __nv_bfloat16* __restrict__ WrTh, const __nv_bfloat16* __restrict__ WrTl,
    const float* __restrict__ bias, __nv_bfloat16* __restrict__ out,
    float* __restrict__ pool)
{
    __shared__ char sAh[TILE_BYTES];
    __shared__ char sWh[TILE_BYTES];
    __shared__ char sWl[TILE_BYTES];
    __shared__ float spool[128];

    const int t    = threadIdx.x;
    const int wid  = t >> 5;
    const int lane = t & 31;
    const int grp  = lane >> 2;
    const int tig  = lane & 3;
    const int warpM = wid >> 2;
    const int warpN = wid & 3;
    const int m0 = blockIdx.x * 128;

    float acc[4][4][4];
#pragma unroll
    for (int i = 0; i < 4; i++)
#pragma unroll
        for (int j = 0; j < 4; j++)
#pragma unroll
            for (int r = 0; r < 4; r++) acc[i][j][r] = 0.f;

    const int arow  = t >> 1;
    const int ahalf = t & 1;
    const int gr = m0 + arow;

    for (int c = 0; c < 8; c++) {
        const bool fh = (c < 4);          // aggregation half of K
        const int k0 = (c & 3) * 32;

        // ---- load A chunk (bf16 straight copy): rows 128 x 32 k
        {
            const __nv_bfloat16* srcb = fh ? aggr : xin;
            const uint4* srcp = (const uint4*)(srcb + (size_t)gr * 128 + k0 + ahalf * 16);
            uint4 v0 = make_uint4(0u, 0u, 0u, 0u);
            uint4 v1 = make_uint4(0u, 0u, 0u, 0u);
            if (gr < N_NODES) { v0 = __ldg(srcp); v1 = __ldg(srcp + 1); }
            char* row = sAh + arow * A_STRIDE + ahalf * 32;
            *((uint4*)(row + 0))  = v0;
            *((uint4*)(row + 16)) = v1;
        }
        // ---- load W chunk: 128 n-rows x 32 k bf16, hi (t<128) / lo (t>=128)
        {
            int n = t & 127;
            const __nv_bfloat16* wsrc =
                fh ? ((t < 128) ? WlTh : WlTl) : ((t < 128) ? WrTh : WrTl);
            char* wdst = (t < 128) ? sWh : sWl;
            const uint4* src16 = (const uint4*)(wsrc + n * 128 + k0);
            uint4 v0 = __ldg(src16 + 0);
            uint4 v1 = __ldg(src16 + 1);
            uint4 v2 = __ldg(src16 + 2);
            uint4 v3 = __ldg(src16 + 3);
            char* row = wdst + n * A_STRIDE;
            *((uint4*)(row + 0))  = v0;
            *((uint4*)(row + 16)) = v1;
            *((uint4*)(row + 32)) = v2;
            *((uint4*)(row + 48)) = v3;
        }
        __syncthreads();

        // ---- compute: 2 k16-steps
#pragma unroll
        for (int kk = 0; kk < 2; kk++) {
            const int kb = kk * 32;
            uint32_t ah[4][4];
#pragma unroll
            for (int mi = 0; mi < 4; mi++) {
                int rb = warpM * 64 + mi * 16;
                int r1 = (rb + grp) * A_STRIDE + kb + tig * 4;
                int r2 = (rb + grp + 8) * A_STRIDE + kb + tig * 4;
                ah[mi][0] = *((uint32_t*)(sAh + r1));
                ah[mi][1] = *((uint32_t*)(sAh + r2));
                ah[mi][2] = *((uint32_t*)(sAh + r1 + 16));
                ah[mi][3] = *((uint32_t*)(sAh + r2 + 16));
            }
#pragma unroll
            for (int ni = 0; ni < 4; ni++) {
                int nrow = warpN * 32 + ni * 8 + grp;
                int wo = nrow * A_STRIDE + kb + tig * 4;
                uint32_t wh0 = *((uint32_t*)(sWh + wo));
                uint32_t wh1 = *((uint32_t*)(sWh + wo + 16));
                uint32_t wl0 = *((uint32_t*)(sWl + wo));
                uint32_t wl1 = *((uint32_t*)(sWl + wo + 16));
#pragma unroll
                for (int mi = 0; mi < 4; mi++) {
                    mma_bf16(acc[mi][ni], ah[mi], wh0, wh1);
                    mma_bf16(acc[mi][ni], ah[mi], wl0, wl1);
                }
            }
        }
        __syncthreads();
    }

    if (POOL) {
        if (t < 128) spool[t] = 0.f;
        __syncthreads();
    }

    // ---- epilogue: bias + relu; stores only when output is live (!POOL)
    float2 psum[4];
    if (POOL)
#pragma unroll
        for (int ni = 0; ni < 4; ni++) psum[ni] = make_float2(0.f, 0.f);

#pragma unroll
    for (int mi = 0; mi < 4; mi++) {
        int r1 = m0 + warpM * 64 + mi * 16 + grp;
        int r2 = r1 + 8;
#pragma unroll
        for (int ni = 0; ni < 4; ni++) {
            int col = warpN * 32 + ni * 8 + tig * 2;
            float b0 = __ldg(&bias[col]);
            float b1 = __ldg(&bias[col + 1]);
            if (r1 < N_NODES) {
                float f0 = fmaxf(acc[mi][ni][0] + b0, 0.f);
                float f1 = fmaxf(acc[mi][ni][1] + b1, 0.f);
                if (POOL) {
                    psum[ni].x += f0; psum[ni].y += f1;
                } else {
                    *((__nv_bfloat162*)(out + (size_t)r1 * 128 + col)) =
                        __floats2bfloat162_rn(f0, f1);
                }
            }
            if (r2 < N_NODES) {
                float f2 = fmaxf(acc[mi][ni][2] + b0, 0.f);
                float f3 = fmaxf(acc[mi][ni][3] + b1, 0.f);
                if (POOL) {
                    psum[ni].x += f2; psum[ni].y += f3;
                } else {
                    *((__nv_bfloat162*)(out + (size_t)r2 * 128 + col)) =
                        __floats2bfloat162_rn(f2, f3);
                }
            }
        }
    }

    if (POOL) {
        // reduce across grp lanes (lane = grp*4 + tig): xor over bits 2..4
#pragma unroll
        for (int ni = 0; ni < 4; ni++) {
#pragma unroll
            for (int off = 4; off < 32; off <<= 1) {
                psum[ni].x += __shfl_xor_sync(0xffffffffu, psum[ni].x, off);
                psum[ni].y += __shfl_xor_sync(0xffffffffu, psum[ni].y, off);
            }
        }
        if (grp == 0) {
#pragma unroll
            for (int ni = 0; ni < 4; ni++) {
                int col = warpN * 32 + ni * 8 + tig * 2;
                atomicAdd(&spool[col],     psum[ni].x);
                atomicAdd(&spool[col + 1], psum[ni].y);
            }
        }
        __syncthreads();
        if (t < 128) atomicAdd(&pool[t], spool[t]);
    }
}

// ===========================================================================
__global__ void head_kernel(const float* __restrict__ pool,
                            const float* __restrict__ Wg,
                            const float* __restrict__ bg,
                            float* __restrict__ out) {
    int j = threadIdx.x;
    if (j >= D_LAT) return;
    float acc = bg[j];
    const float invn = 1.0f / (float)N_NODES;
#pragma unroll 8
    for (int k = 0; k < D; k++)
        acc += (pool[k] * invn) * Wg[k * D_LAT + j];
    out[j] = 1.0f / (1.0f + expf(-acc));
}

// ===========================================================================
extern "C" void kernel_launch(void* const* d_in, const int* in_sizes, int n_in,
                              void* d_out, int out_size) {
    const float* x   = (const float*)d_in[0];
    const int*   ei  = (const int*)d_in[1];
    const float* b1  = (const float*)d_in[4];
    const float* b2  = (const float*)d_in[7];
    const float* b3  = (const float*)d_in[10];
    const float* Wg  = (const float*)d_in[11];
    const float* bg  = (const float*)d_in[12];
    float* out = (float*)d_out;

    const int* src = ei;
    const int* dst = ei + N_EDGES;

    float *pool;
    __nv_bfloat16 *xbf, *aggr, *hA, *hB, *wh, *wl;
    int *deg, *offs, *cursor, *part, *perm;
    cudaGetSymbolAddress((void**)&xbf,    g_xbf);
    cudaGetSymbolAddress((void**)&aggr,   g_aggr);
    cudaGetSymbolAddress((void**)&hA,     g_hA);
    cudaGetSymbolAddress((void**)&hB,     g_hB);
    cudaGetSymbolAddress((void**)&pool,   g_pool);
    cudaGetSymbolAddress((void**)&deg,    g_deg);
    cudaGetSymbolAddress((void**)&offs,   g_offs);
    cudaGetSymbolAddress((void**)&cursor, g_cursor);
    cudaGetSymbolAddress((void**)&part,   g_part);
    cudaGetSymbolAddress((void**)&perm,   g_perm);
    cudaGetSymbolAddress((void**)&wh,     g_wh);
    cudaGetSymbolAddress((void**)&wl,     g_wl);

    const int gemm_blocks = (N_NODES + 127) / 128;      // 782
    const int aggr_blocks = (N_NODES + 7) / 8;          // 12500
    const int edge4_blocks = (N_EDGES / 4 + 255) / 256; // 1563

#define WTH(m) (wh + (size_t)(m) * 16384)
#define WTL(m) (wl + (size_t)(m) * 16384)

    // 1: setup (weight prep + x conversion + deg/pool zero)
    setup_kernel<<<(SETUP_TOTAL + 255) / 256, 256>>>(
        (const float*)d_in[2], (const float*)d_in[3],
        (const float*)d_in[5], (const float*)d_in[6],
        (const float*)d_in[8], (const float*)d_in[9],
        wh, wl, (const float4*)x, (uint2*)xbf, deg, pool);
    // 2-5: CSR build
    count_kernel<<<edge4_blocks, 256>>>((const int4*)dst, deg);
    scan1_kernel<<<SCAN_BLOCKS, 256>>>(deg, offs, cursor, part);
    scan2_kernel<<<1, 512>>>(part);
    permute_kernel<<<edge4_blocks, 256>>>((const int4*)src, (const int4*)dst,
                                          cursor, part, perm);

    // layer 1
    gather_aggr<<<aggr_blocks, 256>>>(xbf, perm, offs, part, deg, aggr);
    sage_gemm_mma_t<false><<<gemm_blocks, 256>>>(
        aggr, xbf, WTH(0), WTL(0), WTH(1), WTL(1), b1, hA, pool);

    // layer 2
    gather_aggr<<<aggr_blocks, 256>>>(hA, perm, offs, part, deg, aggr);
    sage_gemm_mma_t<false><<<gemm_blocks, 256>>>(
        aggr, hA, WTH(2), WTL(2), WTH(3), WTL(3), b2, hB, pool);

    // layer 3: output features dead -> no stores, pool fused
    gather_aggr<<<aggr_blocks, 256>>>(hB, perm, offs, part, deg, aggr);
    sage_gemm_mma_t<true><<<gemm_blocks, 256>>>(
        aggr, hB, WTH(4), WTL(4), WTH(5), WTL(5), b3, hA, pool);

    // head
    head_kernel<<<1, 64>>>(pool, Wg, bg, out);
}